// round 8
// baseline (speedup 1.0000x reference)
#include <cuda_runtime.h>

// StateSpaceDiffusionModel: y[b,h,:] = causal_conv(u[b,h,:], f[h,:])
// reduced exactly to a scalar order-64 IIR+FIR (transposed direct form II):
//   y_t = c0*u_t + S[1]
//   S[i] <- S[i+1] + A'[i]*y_t + C'[i]*u_t   (merged delay line, i=1..64)
// A'[i] = a_{i-1} (1<=i<=64), C'[i] = c_i (1<=i<=63).
//
// REDUNDANT-HEAD layout (this round): every lane of an 8-lane group keeps
// head slots 1..4 (identical in all lanes -> y computed locally, NO y
// broadcast on the loop-carried path). Tail slots 5..68 distributed,
// 4 dup-style pairs per lane. The only shuffles move one-iteration-old
// state with >=2 iterations of slack (latency-tolerant).

#define HH 512
#define NN 64
#define BB 16
#define LL 2048

__device__ float g_a[HH * NN];
__device__ float g_c[HH * NN];

// ---------------- Kernel 1: per-head coefficients (trivial) ----------------
__global__ void coef_kernel(const float* __restrict__ k) {
    __shared__ float sh[NN];
    __shared__ float shd[NN];
    __shared__ float shP[NN];
    __shared__ float shsum;
    int h = blockIdx.x;
    int j = threadIdx.x;
    float kv = k[h * NN + j];
    float kc = fminf(fmaxf(kv, 1.0f / 16.0f), 1.0f);
    sh[j] = kc;
    __syncthreads();
    if (j == 0) {
        float s = 0.f;
        for (int i = 0; i < NN; i++) s += sh[i];
        shsum = s;
    }
    __syncthreads();
    float kn = kc / shsum;                       // L1-normalized clamped k
    float s = (j < NN - 1) ? (1.0f + kn) : kn;   // column L1 norm of (A + b k^T)
    float w = kn / s;                            // M[0, j]
    shd[j] = 1.0f / s;                           // M[j+1, j] subdiagonal
    __syncthreads();
    if (j == 0) {
        float P = 1.f;
        for (int i = 0; i < NN; i++) { shP[i] = P; P *= shd[i]; }
    }
    __syncthreads();
    float Pj = shP[j];
    g_a[h * NN + j] = w * Pj;    // IIR taps
    g_c[h * NN + j] = kv * Pj;   // FIR taps (original k!)
}

// ---------------- packed f32x2 helpers ----------------
typedef unsigned long long ull;
__device__ __forceinline__ ull pack2(float lo, float hi) {
    ull r; asm("mov.b64 %0, {%1,%2};" : "=l"(r) : "f"(lo), "f"(hi)); return r;
}
__device__ __forceinline__ void unpack2(ull v, float& lo, float& hi) {
    asm("mov.b64 {%0,%1}, %2;" : "=f"(lo), "=f"(hi) : "l"(v));
}
__device__ __forceinline__ ull fma2(ull a, ull b, ull c) {
    ull d; asm("fma.rn.f32x2 %0, %1, %2, %3;" : "=l"(d) : "l"(a), "l"(b), "l"(c)); return d;
}

// ---------------- Kernel 2: redundant-head scan, 8 lanes/seq ---------------
// Warp = 4 sequences x 8 lanes. Per 2-step iteration:
//  head (ALL lanes, identical):
//   y0 = c0*u0 + S1 ; y1 = A'1*y0 + c0*u1 + C'1*u0 + S2
//   P12'' = P34_old + (A'2,A'3)y0d + (A'1,A'2)y1d + (C'2,C'3)u0d + (C'1,C'2)u1d
//   P34'' = bc56    + (A'4,A'5)y0d + (A'3,A'4)y1d + (C'4,C'5)u0d + (C'3,C'4)u1d
//   bc56 = (S5,S6)_old = leader lane's tail pair 0 (shfl, off critical path)
//  tail (lane r owns pairs p=0..3, base slot s = 8r+5+2p):
//   T''[p] = T_old[p+1] + Ae_p*y0d + Ao_p*y1d + Ce_p*u0d + Co_p*u1d
//   T_old[4] = next lane's T_old[0] (shfl_down; zero on r==7)
#define PD 2   // float4 FIFO slots; each slot feeds 2 iterations (4 timesteps)

__global__ void __launch_bounds__(128, 4)
scan_kernel(const float* __restrict__ u, float* __restrict__ y) {
    int warp = blockIdx.x * (blockDim.x >> 5) + (threadIdx.x >> 5);
    int lane = threadIdx.x & 31;
    int g = lane >> 3;   // sequence within warp (0..3)
    int r = lane & 7;    // lane within group (0..7)
    int leader = lane & ~7;
    int seq = warp * 4 + g;           // 0..8191
    int h = seq & (HH - 1);
    const float4* ubase4 = (const float4*)(u + (size_t)seq * LL);
    ull* ybase2 = (ull*)(y + (size_t)seq * LL);

    const float* ah = g_a + h * NN;   // A'(i) = ah[i-1], valid i=1..64
    const float* ch = g_c + h * NN;   // C'(i) = ch[i],   valid i=1..63

    // ---- tail taps: base slot s = 8r+5+2p ----
    ull Ae[4], Ao[4], Ce[4], Co[4], T[4];
#pragma unroll
    for (int p = 0; p < 4; p++) {
        int s = 8 * r + 5 + 2 * p;
        float A0v = (s     <= 64) ? ah[s - 1] : 0.f;   // A'(s)
        float A1v = (s + 1 <= 64) ? ah[s]     : 0.f;   // A'(s+1)
        float A2v = (s + 2 <= 64) ? ah[s + 1] : 0.f;   // A'(s+2)
        float C0v = (s     <= 63) ? ch[s]     : 0.f;   // C'(s)
        float C1v = (s + 1 <= 63) ? ch[s + 1] : 0.f;
        float C2v = (s + 2 <= 63) ? ch[s + 2] : 0.f;
        Ae[p] = pack2(A1v, A2v);   // * y0d
        Ao[p] = pack2(A0v, A1v);   // * y1d
        Ce[p] = pack2(C1v, C2v);   // * u0d
        Co[p] = pack2(C0v, C1v);   // * u1d
        T[p] = 0ull;
    }

    // ---- head taps (all lanes identical) ----
    float A1h = ah[0], A2h = ah[1], A3h = ah[2], A4h = ah[3], A5h = ah[4];
    float c0h = ch[0], C1h = ch[1], C2h = ch[2], C3h = ch[3], C4h = ch[4], C5h = ch[5];
    ull HA12e = pack2(A2h, A3h);   // P12: * y0d
    ull HA12o = pack2(A1h, A2h);   //      * y1d
    ull HC12e = pack2(C2h, C3h);   //      * u0d
    ull HC12o = pack2(C1h, C2h);   //      * u1d
    ull HA34e = pack2(A4h, A5h);   // P34: * y0d
    ull HA34o = pack2(A3h, A4h);   //      * y1d
    ull HC34e = pack2(C4h, C5h);   //      * u0d
    ull HC34o = pack2(C3h, C4h);   //      * u1d
    ull P12 = 0ull, P34 = 0ull;
    float S1 = 0.f, S2 = 0.f;

    // prologue: fill FIFO (each slot = 4 timesteps = 2 iterations)
    float4 buf[PD];
#pragma unroll
    for (int j = 0; j < PD; j++) buf[j] = ubase4[j];

    const int NQ = LL / 4;  // 512 float4 chunks
    for (int q0 = 0; q0 < NQ; q0 += PD) {
#pragma unroll
        for (int j = 0; j < PD; j++) {
            int q = q0 + j;
            float4 cur = buf[j];
            int qp = q + PD; if (qp > NQ - 1) qp = NQ - 1;
            buf[j] = ubase4[qp];   // refill (clamped; unused if OOB)

#pragma unroll
            for (int half = 0; half < 2; half++) {
                float u0 = half ? cur.z : cur.x;
                float u1 = half ? cur.w : cur.y;

                // latency-tolerant shuffles of OLD tail state
                ull bc56 = __shfl_sync(0xffffffffu, T[0], leader);       // (S5,S6)old
                ull tb   = __shfl_down_sync(0xffffffffu, T[0], 1);       // next lane pair0 old
                if (r == 7) tb = 0ull;

                // ---- local y (identical in all lanes of the group) ----
                float y0 = fmaf(c0h, u0, S1);
                float y1 = fmaf(A1h, y0, fmaf(c0h, u1, fmaf(C1h, u0, S2)));

                ull y0d = pack2(y0, y0), y1d = pack2(y1, y1);
                ull u0d = pack2(u0, u0), u1d = pack2(u1, u1);

                // ---- head update (local; P34_old / bc56 as bases) ----
                ull nP12 = fma2(HA12o, y1d, fma2(HA12e, y0d,
                            fma2(HC12o, u1d, fma2(HC12e, u0d, P34))));
                ull nP34 = fma2(HA34o, y1d, fma2(HA34e, y0d,
                            fma2(HC34o, u1d, fma2(HC34e, u0d, bc56))));

                // ---- tail update ----
                ull n0 = fma2(Ao[0], y1d, fma2(Ae[0], y0d,
                          fma2(Co[0], u1d, fma2(Ce[0], u0d, T[1]))));
                ull n1 = fma2(Ao[1], y1d, fma2(Ae[1], y0d,
                          fma2(Co[1], u1d, fma2(Ce[1], u0d, T[2]))));
                ull n2 = fma2(Ao[2], y1d, fma2(Ae[2], y0d,
                          fma2(Co[2], u1d, fma2(Ce[2], u0d, T[3]))));
                ull n3 = fma2(Ao[3], y1d, fma2(Ae[3], y0d,
                          fma2(Co[3], u1d, fma2(Ce[3], u0d, tb))));
                T[0] = n0; T[1] = n1; T[2] = n2; T[3] = n3;

                P12 = nP12; P34 = nP34;
                unpack2(P12, S1, S2);

                if (r == 0)
                    ybase2[2 * q + half] = pack2(y0, y1);
            }
        }
    }
}

extern "C" void kernel_launch(void* const* d_in, const int* in_sizes, int n_in,
                              void* d_out, int out_size) {
    const float* u = (const float*)d_in[0];
    const float* k = (const float*)d_in[1];
    if (n_in >= 2 && in_sizes[0] == HH * NN) {  // defensive: swap if order differs
        u = (const float*)d_in[1];
        k = (const float*)d_in[0];
    }
    float* y = (float*)d_out;

    coef_kernel<<<HH, NN>>>(k);
    // 8192 sequences, 4 per warp, 4 warps per 128-thread CTA -> 512 CTAs
    scan_kernel<<<(BB * HH) / 16, 128>>>(u, y);
}

// round 9
// speedup vs baseline: 1.0093x; 1.0093x over previous
#include <cuda_runtime.h>

// StateSpaceDiffusionModel: y[b,h,:] = causal_conv(u[b,h,:], f[h,:])
// reduced exactly to a scalar order-64 IIR+FIR (transposed direct form II):
//   y_t = c0*u_t + S[1]
//   S[i] <- S[i+1] + A'[i]*y_t + C'[i]*u_t   (merged delay line, i=1..64)
// A'[i] = a_{i-1} (1<=i<=64), C'[i] = c_i (1<=i<=63).
//
// REDUNDANT-HEAD layout (this round): every lane of an 8-lane group keeps
// head slots 1..4 (identical in all lanes -> y computed locally, NO y
// broadcast on the loop-carried path). Tail slots 5..68 distributed,
// 4 dup-style pairs per lane. The only shuffles move one-iteration-old
// state with >=2 iterations of slack (latency-tolerant).

#define HH 512
#define NN 64
#define BB 16
#define LL 2048

__device__ float g_a[HH * NN];
__device__ float g_c[HH * NN];

// ---------------- Kernel 1: per-head coefficients (trivial) ----------------
__global__ void coef_kernel(const float* __restrict__ k) {
    __shared__ float sh[NN];
    __shared__ float shd[NN];
    __shared__ float shP[NN];
    __shared__ float shsum;
    int h = blockIdx.x;
    int j = threadIdx.x;
    float kv = k[h * NN + j];
    float kc = fminf(fmaxf(kv, 1.0f / 16.0f), 1.0f);
    sh[j] = kc;
    __syncthreads();
    if (j == 0) {
        float s = 0.f;
        for (int i = 0; i < NN; i++) s += sh[i];
        shsum = s;
    }
    __syncthreads();
    float kn = kc / shsum;                       // L1-normalized clamped k
    float s = (j < NN - 1) ? (1.0f + kn) : kn;   // column L1 norm of (A + b k^T)
    float w = kn / s;                            // M[0, j]
    shd[j] = 1.0f / s;                           // M[j+1, j] subdiagonal
    __syncthreads();
    if (j == 0) {
        float P = 1.f;
        for (int i = 0; i < NN; i++) { shP[i] = P; P *= shd[i]; }
    }
    __syncthreads();
    float Pj = shP[j];
    g_a[h * NN + j] = w * Pj;    // IIR taps
    g_c[h * NN + j] = kv * Pj;   // FIR taps (original k!)
}

// ---------------- packed f32x2 helpers ----------------
typedef unsigned long long ull;
__device__ __forceinline__ ull pack2(float lo, float hi) {
    ull r; asm("mov.b64 %0, {%1,%2};" : "=l"(r) : "f"(lo), "f"(hi)); return r;
}
__device__ __forceinline__ void unpack2(ull v, float& lo, float& hi) {
    asm("mov.b64 {%0,%1}, %2;" : "=f"(lo), "=f"(hi) : "l"(v));
}
__device__ __forceinline__ ull fma2(ull a, ull b, ull c) {
    ull d; asm("fma.rn.f32x2 %0, %1, %2, %3;" : "=l"(d) : "l"(a), "l"(b), "l"(c)); return d;
}

// ---------------- Kernel 2: redundant-head scan, 8 lanes/seq ---------------
// Warp = 4 sequences x 8 lanes. Per 2-step iteration:
//  head (ALL lanes, identical):
//   y0 = c0*u0 + S1 ; y1 = A'1*y0 + c0*u1 + C'1*u0 + S2
//   P12'' = P34_old + (A'2,A'3)y0d + (A'1,A'2)y1d + (C'2,C'3)u0d + (C'1,C'2)u1d
//   P34'' = bc56    + (A'4,A'5)y0d + (A'3,A'4)y1d + (C'4,C'5)u0d + (C'3,C'4)u1d
//   bc56 = (S5,S6)_old = leader lane's tail pair 0 (shfl, off critical path)
//  tail (lane r owns pairs p=0..3, base slot s = 8r+5+2p):
//   T''[p] = T_old[p+1] + Ae_p*y0d + Ao_p*y1d + Ce_p*u0d + Co_p*u1d
//   T_old[4] = next lane's T_old[0] (shfl_down; zero on r==7)
#define PD 2   // float4 FIFO slots; each slot feeds 2 iterations (4 timesteps)

__global__ void __launch_bounds__(128, 4)
scan_kernel(const float* __restrict__ u, float* __restrict__ y) {
    int warp = blockIdx.x * (blockDim.x >> 5) + (threadIdx.x >> 5);
    int lane = threadIdx.x & 31;
    int g = lane >> 3;   // sequence within warp (0..3)
    int r = lane & 7;    // lane within group (0..7)
    int leader = lane & ~7;
    int seq = warp * 4 + g;           // 0..8191
    int h = seq & (HH - 1);
    const float4* ubase4 = (const float4*)(u + (size_t)seq * LL);
    ull* ybase2 = (ull*)(y + (size_t)seq * LL);

    const float* ah = g_a + h * NN;   // A'(i) = ah[i-1], valid i=1..64
    const float* ch = g_c + h * NN;   // C'(i) = ch[i],   valid i=1..63

    // ---- tail taps: base slot s = 8r+5+2p ----
    ull Ae[4], Ao[4], Ce[4], Co[4], T[4];
#pragma unroll
    for (int p = 0; p < 4; p++) {
        int s = 8 * r + 5 + 2 * p;
        float A0v = (s     <= 64) ? ah[s - 1] : 0.f;   // A'(s)
        float A1v = (s + 1 <= 64) ? ah[s]     : 0.f;   // A'(s+1)
        float A2v = (s + 2 <= 64) ? ah[s + 1] : 0.f;   // A'(s+2)
        float C0v = (s     <= 63) ? ch[s]     : 0.f;   // C'(s)
        float C1v = (s + 1 <= 63) ? ch[s + 1] : 0.f;
        float C2v = (s + 2 <= 63) ? ch[s + 2] : 0.f;
        Ae[p] = pack2(A1v, A2v);   // * y0d
        Ao[p] = pack2(A0v, A1v);   // * y1d
        Ce[p] = pack2(C1v, C2v);   // * u0d
        Co[p] = pack2(C0v, C1v);   // * u1d
        T[p] = 0ull;
    }

    // ---- head taps (all lanes identical) ----
    float A1h = ah[0], A2h = ah[1], A3h = ah[2], A4h = ah[3], A5h = ah[4];
    float c0h = ch[0], C1h = ch[1], C2h = ch[2], C3h = ch[3], C4h = ch[4], C5h = ch[5];
    ull HA12e = pack2(A2h, A3h);   // P12: * y0d
    ull HA12o = pack2(A1h, A2h);   //      * y1d
    ull HC12e = pack2(C2h, C3h);   //      * u0d
    ull HC12o = pack2(C1h, C2h);   //      * u1d
    ull HA34e = pack2(A4h, A5h);   // P34: * y0d
    ull HA34o = pack2(A3h, A4h);   //      * y1d
    ull HC34e = pack2(C4h, C5h);   //      * u0d
    ull HC34o = pack2(C3h, C4h);   //      * u1d
    ull P12 = 0ull, P34 = 0ull;
    float S1 = 0.f, S2 = 0.f;

    // prologue: fill FIFO (each slot = 4 timesteps = 2 iterations)
    float4 buf[PD];
#pragma unroll
    for (int j = 0; j < PD; j++) buf[j] = ubase4[j];

    const int NQ = LL / 4;  // 512 float4 chunks
    for (int q0 = 0; q0 < NQ; q0 += PD) {
#pragma unroll
        for (int j = 0; j < PD; j++) {
            int q = q0 + j;
            float4 cur = buf[j];
            int qp = q + PD; if (qp > NQ - 1) qp = NQ - 1;
            buf[j] = ubase4[qp];   // refill (clamped; unused if OOB)

#pragma unroll
            for (int half = 0; half < 2; half++) {
                float u0 = half ? cur.z : cur.x;
                float u1 = half ? cur.w : cur.y;

                // latency-tolerant shuffles of OLD tail state
                ull bc56 = __shfl_sync(0xffffffffu, T[0], leader);       // (S5,S6)old
                ull tb   = __shfl_down_sync(0xffffffffu, T[0], 1);       // next lane pair0 old
                if (r == 7) tb = 0ull;

                // ---- local y (identical in all lanes of the group) ----
                float y0 = fmaf(c0h, u0, S1);
                float y1 = fmaf(A1h, y0, fmaf(c0h, u1, fmaf(C1h, u0, S2)));

                ull y0d = pack2(y0, y0), y1d = pack2(y1, y1);
                ull u0d = pack2(u0, u0), u1d = pack2(u1, u1);

                // ---- head update (local; P34_old / bc56 as bases) ----
                ull nP12 = fma2(HA12o, y1d, fma2(HA12e, y0d,
                            fma2(HC12o, u1d, fma2(HC12e, u0d, P34))));
                ull nP34 = fma2(HA34o, y1d, fma2(HA34e, y0d,
                            fma2(HC34o, u1d, fma2(HC34e, u0d, bc56))));

                // ---- tail update ----
                ull n0 = fma2(Ao[0], y1d, fma2(Ae[0], y0d,
                          fma2(Co[0], u1d, fma2(Ce[0], u0d, T[1]))));
                ull n1 = fma2(Ao[1], y1d, fma2(Ae[1], y0d,
                          fma2(Co[1], u1d, fma2(Ce[1], u0d, T[2]))));
                ull n2 = fma2(Ao[2], y1d, fma2(Ae[2], y0d,
                          fma2(Co[2], u1d, fma2(Ce[2], u0d, T[3]))));
                ull n3 = fma2(Ao[3], y1d, fma2(Ae[3], y0d,
                          fma2(Co[3], u1d, fma2(Ce[3], u0d, tb))));
                T[0] = n0; T[1] = n1; T[2] = n2; T[3] = n3;

                P12 = nP12; P34 = nP34;
                unpack2(P12, S1, S2);

                if (r == 0)
                    ybase2[2 * q + half] = pack2(y0, y1);
            }
        }
    }
}

extern "C" void kernel_launch(void* const* d_in, const int* in_sizes, int n_in,
                              void* d_out, int out_size) {
    const float* u = (const float*)d_in[0];
    const float* k = (const float*)d_in[1];
    if (n_in >= 2 && in_sizes[0] == HH * NN) {  // defensive: swap if order differs
        u = (const float*)d_in[1];
        k = (const float*)d_in[0];
    }
    float* y = (float*)d_out;

    coef_kernel<<<HH, NN>>>(k);
    // 8192 sequences, 4 per warp, 4 warps per 128-thread CTA -> 512 CTAs
    scan_kernel<<<(BB * HH) / 16, 128>>>(u, y);
}